// round 14
// baseline (speedup 1.0000x reference)
#include <cuda_runtime.h>
#include <cuda_bf16.h>
#include <cstdint>

#define D 128
#define NTHREADS 256
#define MAXN 50000
#define ETILE 64
#define NT 64
#define A_STRIDE 136

// ---------------------------------------------------------------------------
// static scratch
// ---------------------------------------------------------------------------
__device__ float g_P1[(size_t)MAXN * D];   // h @ We1[0:128] + be1
__device__ float g_P2[(size_t)MAXN * D];   // h @ We1[128:256]; later: hid
__device__ float g_Q1[(size_t)MAXN * D];   // h @ Wn1[0:128] + bn1
__device__ float g_agg[(size_t)MAXN * D];  // sum of hid per node
__device__ float g_deg[MAXN];              // degree (as float)
__device__ float g_bf[D];                  // be2 @ Wc1 + bc1
__device__ float g_bb[D];                  // be2 @ Wn1b
__device__ float g_Wf[D * D];              // We2 @ Wc1   (k-major)
__device__ float g_Wfn[D * D];             // We2 @ Wn1b  (k-major)
// B fragments in mma order: [hi/lo][nb(8)][ks(8)][lane(32)][4] u32 each
__device__ uint32_t g_frag_Wf[2 * 8 * 8 * 32 * 4];
__device__ uint32_t g_frag_Wfn[2 * 8 * 8 * 32 * 4];
__device__ uint32_t g_frag_E1a[2 * 8 * 8 * 32 * 4];
__device__ uint32_t g_frag_E1b[2 * 8 * 8 * 32 * 4];
__device__ uint32_t g_frag_N1a[2 * 8 * 8 * 32 * 4];
__device__ uint32_t g_frag_N2[2 * 8 * 8 * 32 * 4];

__device__ __forceinline__ float frelu(float x) { return x > 0.f ? x : 0.f; }

__device__ __forceinline__ uint32_t smem_u32(const void* p) {
    uint32_t a;
    asm("{ .reg .u64 t; cvta.to.shared.u64 t, %1; cvt.u32.u64 %0, t; }"
        : "=r"(a) : "l"(p));
    return a;
}

__device__ __forceinline__ void ldmat_x4(uint32_t& a0, uint32_t& a1,
                                         uint32_t& a2, uint32_t& a3,
                                         uint32_t addr) {
    asm volatile(
        "ldmatrix.sync.aligned.m8n8.x4.shared.b16 {%0,%1,%2,%3}, [%4];"
        : "=r"(a0), "=r"(a1), "=r"(a2), "=r"(a3) : "r"(addr));
}

__device__ __forceinline__ void mma_bf16(float d[4], uint32_t a0, uint32_t a1,
                                         uint32_t a2, uint32_t a3,
                                         uint32_t b0, uint32_t b1) {
    asm volatile(
        "mma.sync.aligned.m16n8k16.row.col.f32.bf16.bf16.f32 "
        "{%0,%1,%2,%3}, {%4,%5,%6,%7}, {%8,%9}, {%0,%1,%2,%3};"
        : "+f"(d[0]), "+f"(d[1]), "+f"(d[2]), "+f"(d[3])
        : "r"(a0), "r"(a1), "r"(a2), "r"(a3), "r"(b0), "r"(b1));
}

__device__ __forceinline__ void red_v4(float* dst, float4 v) {
    asm volatile(
        "red.global.add.v4.f32 [%0], {%1, %2, %3, %4};"
        :: "l"(dst), "f"(v.x), "f"(v.y), "f"(v.z), "f"(v.w) : "memory");
}

// ---------------------------------------------------------------------------
// 3-pass bf16x3 GEMM as a MACRO. Needs in scope: wid, lane, arow, acol8.
// ---------------------------------------------------------------------------
#define RUN_GEMM3(FRAG, AHI, ALO, DACC)                                        \
    do {                                                                       \
        _Pragma("unroll") for (int mt = 0; mt < 4; ++mt)                       \
            _Pragma("unroll") for (int nt = 0; nt < 2; ++nt)                   \
                _Pragma("unroll") for (int i = 0; i < 4; ++i)                  \
                    DACC[mt][nt][i] = 0.f;                                     \
        _Pragma("unroll") for (int pass = 0; pass < 3; ++pass) {               \
            const uint32_t abase_ = (pass == 1) ? (ALO) : (AHI);               \
            const int psel_ = (pass == 2) ? 1 : 0;                             \
            _Pragma("unroll") for (int ks = 0; ks < 8; ++ks) {                 \
                uint4 bv_ = *reinterpret_cast<const uint4*>(                   \
                    (FRAG) +                                                   \
                    ((((size_t)psel_ * 8 + wid) * 8 + ks) * 32 + lane) * 4);   \
                _Pragma("unroll") for (int mt = 0; mt < 4; ++mt) {             \
                    uint32_t addr_ = abase_ +                                  \
                        (uint32_t)((mt * 16 + arow) * (A_STRIDE * 2) +         \
                                   (ks * 16 + acol8) * 2);                     \
                    uint32_t a0_, a1_, a2_, a3_;                               \
                    ldmat_x4(a0_, a1_, a2_, a3_, addr_);                       \
                    mma_bf16(DACC[mt][0], a0_, a1_, a2_, a3_, bv_.x, bv_.y);   \
                    mma_bf16(DACC[mt][1], a0_, a1_, a2_, a3_, bv_.z, bv_.w);   \
                }                                                              \
            }                                                                  \
        }                                                                      \
    } while (0)

// store DACC (+ optional bias) to row-major fp32 out. Needs rb, nb, g, t, N.
#define STORE_OUT(OUT, BIAS, HASB, DACC)                                       \
    do {                                                                       \
        _Pragma("unroll") for (int mt = 0; mt < 4; ++mt) {                     \
            _Pragma("unroll") for (int nt = 0; nt < 2; ++nt) {                 \
                int c_ = nb + nt * 8 + t * 2;                                  \
                float b0_ = 0.f, b1_ = 0.f;                                    \
                if (HASB) {                                                    \
                    b0_ = __ldg((BIAS) + c_);                                  \
                    b1_ = __ldg((BIAS) + c_ + 1);                              \
                }                                                              \
                int r0_ = rb + mt * 16 + g;                                    \
                int r1_ = r0_ + 8;                                             \
                if (r0_ < N)                                                   \
                    *reinterpret_cast<float2*>((OUT) + (size_t)r0_ * D + c_) = \
                        make_float2(DACC[mt][nt][0] + b0_,                     \
                                    DACC[mt][nt][1] + b1_);                    \
                if (r1_ < N)                                                   \
                    *reinterpret_cast<float2*>((OUT) + (size_t)r1_ * D + c_) = \
                        make_float2(DACC[mt][nt][2] + b0_,                     \
                                    DACC[mt][nt][3] + b1_);                    \
            }                                                                  \
        }                                                                      \
    } while (0)

// stage 64 rows of fp32 src into bf16 hi/lo A tiles at sm[0]/sm[ALO_OFF]
#define STAGE_A(SRC, ALO_OFF)                                                  \
    do {                                                                       \
        for (int idx = tid; idx < NT * 32; idx += NTHREADS) {                  \
            int e_ = idx >> 5, k4_ = idx & 31;                                 \
            int row_ = rb + e_;                                                \
            float4 v_ = make_float4(0.f, 0.f, 0.f, 0.f);                       \
            if (row_ < N)                                                      \
                v_ = *reinterpret_cast<const float4*>((SRC) +                  \
                                                      (size_t)row_ * D +       \
                                                      k4_ * 4);                \
            __nv_bfloat162 hp0_, hp1_, lp0_, lp1_;                             \
            hp0_.x = __float2bfloat16(v_.x);                                   \
            hp0_.y = __float2bfloat16(v_.y);                                   \
            hp1_.x = __float2bfloat16(v_.z);                                   \
            hp1_.y = __float2bfloat16(v_.w);                                   \
            lp0_.x = __float2bfloat16(v_.x - __bfloat162float(hp0_.x));        \
            lp0_.y = __float2bfloat16(v_.y - __bfloat162float(hp0_.y));        \
            lp1_.x = __float2bfloat16(v_.z - __bfloat162float(hp1_.x));        \
            lp1_.y = __float2bfloat16(v_.w - __bfloat162float(hp1_.y));        \
            size_t boff_ = ((size_t)e_ * A_STRIDE + k4_ * 4) * 2;              \
            *reinterpret_cast<__nv_bfloat162*>(sm + boff_) = hp0_;             \
            *reinterpret_cast<__nv_bfloat162*>(sm + boff_ + 4) = hp1_;         \
            *reinterpret_cast<__nv_bfloat162*>(sm + (ALO_OFF) + boff_) = lp0_; \
            *reinterpret_cast<__nv_bfloat162*>(sm + (ALO_OFF) + boff_ + 4) =   \
                lp1_;                                                          \
        }                                                                      \
    } while (0)

// ---------------------------------------------------------------------------
// prep_gemm: Wf = We2 @ Wc1, Wfn = We2 @ Wn1b (k-major fp32), bf, bb
// ---------------------------------------------------------------------------
__global__ void prep_gemm(const float* __restrict__ We2,
                          const float* __restrict__ be2,
                          const float* __restrict__ Wc1,
                          const float* __restrict__ bc1,
                          const float* __restrict__ Wn1) {
    int k = blockIdx.x;
    int j = threadIdx.x;
    const float* Wn1b = Wn1 + (size_t)128 * D;
    float a1 = 0.f, a2 = 0.f;
#pragma unroll 4
    for (int i = 0; i < D; ++i) {
        float w = We2[k * D + i];
        a1 += w * Wc1[i * D + j];
        a2 += w * Wn1b[i * D + j];
    }
    g_Wf[k * D + j] = a1;
    g_Wfn[k * D + j] = a2;
    if (k == 0) {
        float b1 = bc1[j], b2 = 0.f;
#pragma unroll 4
        for (int i = 0; i < D; ++i) {
            float b = be2[i];
            b1 += b * Wc1[i * D + j];
            b2 += b * Wn1b[i * D + j];
        }
        g_bf[j] = b1;
        g_bb[j] = b2;
    }
}

// ---------------------------------------------------------------------------
// pack_all: 6 weight matrices -> bf16 hi/lo mma B-fragments (device symbols)
// ---------------------------------------------------------------------------
__device__ __forceinline__ uint32_t wbits(const float* __restrict__ W, int c,
                                          int r, int p) {
    float v = W[c * D + r];
    __nv_bfloat16 hi = __float2bfloat16(v);
    if (p) {
        __nv_bfloat16 lo = __float2bfloat16(v - __bfloat162float(hi));
        return (uint32_t)__bfloat16_as_ushort(lo);
    }
    return (uint32_t)__bfloat16_as_ushort(hi);
}

__global__ void pack_all(const float* __restrict__ We1,
                         const float* __restrict__ Wn1,
                         const float* __restrict__ Wn2) {
    int gidx = blockIdx.x * blockDim.x + threadIdx.x;
    int m = gidx >> 12;
    int idx = gidx & 4095;
    const float* W;
    uint32_t* dst;
    switch (m) {
        case 0: W = g_Wf; dst = g_frag_Wf; break;
        case 1: W = g_Wfn; dst = g_frag_Wfn; break;
        case 2: W = We1; dst = g_frag_E1a; break;
        case 3: W = We1 + (size_t)128 * D; dst = g_frag_E1b; break;
        case 4: W = Wn1; dst = g_frag_N1a; break;
        default: W = Wn2; dst = g_frag_N2; break;
    }
    int lane = idx & 31;
    int ks = (idx >> 5) & 7;
    int nbk = (idx >> 8) & 7;
    int p = idx >> 11;
    int g = lane >> 2, t = lane & 3;
    int col = ks * 16 + t * 2;
    int r0 = nbk * 16 + g, r1 = r0 + 8;
    uint32_t* d = dst + (size_t)idx * 4;
    d[0] = wbits(W, col, r0, p) | (wbits(W, col + 1, r0, p) << 16);
    d[1] = wbits(W, col + 8, r0, p) | (wbits(W, col + 9, r0, p) << 16);
    d[2] = wbits(W, col, r1, p) | (wbits(W, col + 1, r1, p) << 16);
    d[3] = wbits(W, col + 8, r1, p) | (wbits(W, col + 9, r1, p) << 16);
}

// ---------------------------------------------------------------------------
// init
// ---------------------------------------------------------------------------
__global__ void init_kernel(const float* __restrict__ coords,
                            float* __restrict__ out_coords, int N) {
    int total4 = N * (D / 4);
    for (int i = blockIdx.x * blockDim.x + threadIdx.x; i < total4;
         i += gridDim.x * blockDim.x)
        reinterpret_cast<float4*>(g_agg)[i] = make_float4(0.f, 0.f, 0.f, 0.f);
    for (int i = blockIdx.x * blockDim.x + threadIdx.x; i < N;
         i += gridDim.x * blockDim.x)
        g_deg[i] = 0.f;
    int c3 = N * 3;
    for (int i = blockIdx.x * blockDim.x + threadIdx.x; i < c3;
         i += gridDim.x * blockDim.x)
        out_coords[i] = coords[i];
}

// ---------------------------------------------------------------------------
// node_gemm: generic single 128x128 GEMM, selector-dispatched.
// sel 0: g_P1 = h @ E1a + be1     (bias param = be1)
// sel 1: g_P2 = h @ E1b           (no bias)
// sel 2: g_Q1 = h @ N1a + bn1     (bias param = bn1)
// sel 3: out_p = g_P2 @ N2 + bn2  (bias param = bn2; A = hid in g_P2)
// ---------------------------------------------------------------------------
#define NG_OFF_ALO 17408
#define NG_SMEM 34816

__global__ void __launch_bounds__(NTHREADS, 2)
node_gemm(const float* __restrict__ h, const float* __restrict__ bias,
          float* __restrict__ out_p, int sel, int N) {
    extern __shared__ char sm[];
    const uint32_t sbase = smem_u32(sm);
    const int tid = threadIdx.x;
    const int rb = blockIdx.x * NT;

    const float* A;
    const uint32_t* frag;
    float* out;
    bool hasb;
    switch (sel) {
        case 0: A = h; frag = g_frag_E1a; out = g_P1; hasb = true; break;
        case 1: A = h; frag = g_frag_E1b; out = g_P2; hasb = false; break;
        case 2: A = h; frag = g_frag_N1a; out = g_Q1; hasb = true; break;
        default: A = g_P2; frag = g_frag_N2; out = out_p; hasb = true; break;
    }

    STAGE_A(A, NG_OFF_ALO);
    __syncthreads();

    const int lane = tid & 31, wid = tid >> 5;
    const int g = lane >> 2, t = lane & 3;
    const int nb = wid * 16, arow = lane & 15, acol8 = (lane >> 4) * 8;

    float dacc[4][2][4];
    RUN_GEMM3(frag, sbase, sbase + NG_OFF_ALO, dacc);
    STORE_OUT(out, bias, hasb, dacc);
}

// ---------------------------------------------------------------------------
// node_hid: hid = relu(Q1 + agg @ Wfn + deg*bb) -> g_P2 (fp32)
// ---------------------------------------------------------------------------
#define NH_OFF_ALO 17408
#define NH_OFF_DEG 34816
#define NH_SMEM 35072

__global__ void __launch_bounds__(NTHREADS, 2)
node_hid(int N) {
    extern __shared__ char sm[];
    float* s_deg = reinterpret_cast<float*>(sm + NH_OFF_DEG);
    const uint32_t sbase = smem_u32(sm);
    const int tid = threadIdx.x;
    const int rb = blockIdx.x * NT;

    STAGE_A(g_agg, NH_OFF_ALO);
    if (tid < NT) {
        int row = rb + tid;
        s_deg[tid] = (row < N) ? g_deg[row] : 0.f;
    }
    __syncthreads();

    const int lane = tid & 31, wid = tid >> 5;
    const int g = lane >> 2, t = lane & 3;
    const int nb = wid * 16, arow = lane & 15, acol8 = (lane >> 4) * 8;

    float dacc[4][2][4];
    RUN_GEMM3(g_frag_Wfn, sbase, sbase + NH_OFF_ALO, dacc);

#pragma unroll
    for (int mt = 0; mt < 4; ++mt) {
        float d0 = s_deg[mt * 16 + g];
        float d1 = s_deg[mt * 16 + g + 8];
        int r0 = rb + mt * 16 + g, r1 = r0 + 8;
#pragma unroll
        for (int nt = 0; nt < 2; ++nt) {
            int c = nb + nt * 8 + t * 2;
            float2 bb = *reinterpret_cast<const float2*>(g_bb + c);
            if (r0 < N) {
                float2 q = *reinterpret_cast<const float2*>(g_Q1 + (size_t)r0 * D + c);
                *reinterpret_cast<float2*>(g_P2 + (size_t)r0 * D + c) =
                    make_float2(frelu(dacc[mt][nt][0] + q.x + d0 * bb.x),
                                frelu(dacc[mt][nt][1] + q.y + d0 * bb.y));
            }
            if (r1 < N) {
                float2 q = *reinterpret_cast<const float2*>(g_Q1 + (size_t)r1 * D + c);
                *reinterpret_cast<float2*>(g_P2 + (size_t)r1 * D + c) =
                    make_float2(frelu(dacc[mt][nt][2] + q.x + d1 * bb.x),
                                frelu(dacc[mt][nt][3] + q.y + d1 * bb.y));
            }
        }
    }
}

// ---------------------------------------------------------------------------
// edge kernel (byte-for-byte R13 structure; proven 2 CTA/SM, no local mem)
// ---------------------------------------------------------------------------
#define OFF_AHI 0
#define OFF_ALO 17408
#define OFF_REL 34816
#define OFF_DIST 35840
#define OFF_W 36096
#define OFF_ROW 36352
#define OFF_COL 36608
#define EDGE_SMEM 36864

__global__ void __launch_bounds__(NTHREADS, 2)
edge_kernel(const float* __restrict__ coords,
            const int* __restrict__ ei,
            const float* __restrict__ We1,
            const float* __restrict__ Wc2,
            float* __restrict__ out_coords,
            int E) {
    extern __shared__ char sm[];
    float* s_rel = reinterpret_cast<float*>(sm + OFF_REL);
    float* s_dist = reinterpret_cast<float*>(sm + OFF_DIST);
    float* s_w = reinterpret_cast<float*>(sm + OFF_W);
    int* s_row = reinterpret_cast<int*>(sm + OFF_ROW);
    int* s_col = reinterpret_cast<int*>(sm + OFF_COL);

    const uint32_t sbase = smem_u32(sm);
    const int tid = threadIdx.x;
    const int e_base = blockIdx.x * ETILE;

    if (tid < ETILE) {
        int ge = e_base + tid;
        int r = 0, c = 0;
        if (ge < E) {
            r = ei[ge];
            c = ei[E + ge];
            atomicAdd(g_deg + r, 1.0f);
        }
        s_row[tid] = r;
        s_col[tid] = c;
        float rx = coords[r * 3 + 0] - coords[c * 3 + 0];
        float ry = coords[r * 3 + 1] - coords[c * 3 + 1];
        float rz = coords[r * 3 + 2] - coords[c * 3 + 2];
        s_rel[tid * 4 + 0] = rx;
        s_rel[tid * 4 + 1] = ry;
        s_rel[tid * 4 + 2] = rz;
        s_dist[tid] = rx * rx + ry * ry + rz * rz;
        s_w[tid] = 0.f;
    }
    __syncthreads();

    {
        const int k4 = tid & 31;
        float4 w4 = __ldg(reinterpret_cast<const float4*>(
            We1 + (size_t)256 * D + k4 * 4));
        for (int idx = tid; idx < ETILE * 32; idx += NTHREADS) {
            int e = idx >> 5;
            float4 hv = make_float4(0.f, 0.f, 0.f, 0.f);
            bool live = (e_base + e < E);
            if (live) {
                int r = s_row[e], c = s_col[e];
                float4 p1 = *reinterpret_cast<const float4*>(
                    g_P1 + (size_t)r * D + k4 * 4);
                float4 p2 = *reinterpret_cast<const float4*>(
                    g_P2 + (size_t)c * D + k4 * 4);
                float d2 = s_dist[e];
                hv.x = frelu(p1.x + p2.x + d2 * w4.x);
                hv.y = frelu(p1.y + p2.y + d2 * w4.y);
                hv.z = frelu(p1.z + p2.z + d2 * w4.z);
                hv.w = frelu(p1.w + p2.w + d2 * w4.w);
                red_v4(g_agg + (size_t)s_row[e] * D + k4 * 4, hv);
            }
            __nv_bfloat162 hp0, hp1, lp0, lp1;
            hp0.x = __float2bfloat16(hv.x);
            hp0.y = __float2bfloat16(hv.y);
            hp1.x = __float2bfloat16(hv.z);
            hp1.y = __float2bfloat16(hv.w);
            lp0.x = __float2bfloat16(hv.x - __bfloat162float(hp0.x));
            lp0.y = __float2bfloat16(hv.y - __bfloat162float(hp0.y));
            lp1.x = __float2bfloat16(hv.z - __bfloat162float(hp1.x));
            lp1.y = __float2bfloat16(hv.w - __bfloat162float(hp1.y));
            size_t boff = ((size_t)e * A_STRIDE + k4 * 4) * 2;
            *reinterpret_cast<__nv_bfloat162*>(sm + OFF_AHI + boff) = hp0;
            *reinterpret_cast<__nv_bfloat162*>(sm + OFF_AHI + boff + 4) = hp1;
            *reinterpret_cast<__nv_bfloat162*>(sm + OFF_ALO + boff) = lp0;
            *reinterpret_cast<__nv_bfloat162*>(sm + OFF_ALO + boff + 4) = lp1;
        }
    }
    __syncthreads();

    const int lane = tid & 31, wid = tid >> 5;
    const int g = lane >> 2, t = lane & 3;
    const int nb = wid * 16;
    const int arow = lane & 15;
    const int acol8 = (lane >> 4) * 8;

    float dacc[4][2][4];
    RUN_GEMM3(g_frag_Wf, sbase + OFF_AHI, sbase + OFF_ALO, dacc);

    {
        float p[4][2];
#pragma unroll
        for (int mt = 0; mt < 4; ++mt) p[mt][0] = p[mt][1] = 0.f;
#pragma unroll
        for (int nt = 0; nt < 2; ++nt) {
            int j = nb + nt * 8 + t * 2;
            float bf0 = __ldg(g_bf + j), bf1 = __ldg(g_bf + j + 1);
            float w0 = __ldg(Wc2 + j), w1 = __ldg(Wc2 + j + 1);
#pragma unroll
            for (int mt = 0; mt < 4; ++mt) {
                p[mt][0] += frelu(dacc[mt][nt][0] + bf0) * w0 +
                            frelu(dacc[mt][nt][1] + bf1) * w1;
                p[mt][1] += frelu(dacc[mt][nt][2] + bf0) * w0 +
                            frelu(dacc[mt][nt][3] + bf1) * w1;
            }
        }
#pragma unroll
        for (int off = 1; off <= 2; off <<= 1)
#pragma unroll
            for (int mt = 0; mt < 4; ++mt) {
                p[mt][0] += __shfl_xor_sync(0xffffffffu, p[mt][0], off);
                p[mt][1] += __shfl_xor_sync(0xffffffffu, p[mt][1], off);
            }
        if (t == 0) {
#pragma unroll
            for (int mt = 0; mt < 4; ++mt) {
                atomicAdd(s_w + mt * 16 + g, p[mt][0]);
                atomicAdd(s_w + mt * 16 + 8 + g, p[mt][1]);
            }
        }
    }
    __syncthreads();

    if (tid < ETILE) {
        int ge = e_base + tid;
        if (ge < E) {
            float w = s_w[tid];
            int r = s_row[tid];
            atomicAdd(out_coords + r * 3 + 0, w * s_rel[tid * 4 + 0]);
            atomicAdd(out_coords + r * 3 + 1, w * s_rel[tid * 4 + 1]);
            atomicAdd(out_coords + r * 3 + 2, w * s_rel[tid * 4 + 2]);
        }
    }
}

// ---------------------------------------------------------------------------
// launch
// ---------------------------------------------------------------------------
extern "C" void kernel_launch(void* const* d_in, const int* in_sizes, int n_in,
                              void* d_out, int out_size) {
    const float* h = (const float*)d_in[0];
    const float* coords = (const float*)d_in[1];
    const int* ei = (const int*)d_in[2];
    const float* We1 = (const float*)d_in[3];
    const float* be1 = (const float*)d_in[4];
    const float* We2 = (const float*)d_in[5];
    const float* be2 = (const float*)d_in[6];
    const float* Wn1 = (const float*)d_in[7];
    const float* bn1 = (const float*)d_in[8];
    const float* Wn2 = (const float*)d_in[9];
    const float* bn2 = (const float*)d_in[10];
    const float* Wc1 = (const float*)d_in[11];
    const float* bc1 = (const float*)d_in[12];
    const float* Wc2 = (const float*)d_in[13];

    int N = in_sizes[0] / D;
    int E = in_sizes[2] / 2;

    float* out_h = (float*)d_out;
    float* out_coords = out_h + (size_t)N * D;

    cudaFuncSetAttribute(edge_kernel, cudaFuncAttributeMaxDynamicSharedMemorySize,
                         EDGE_SMEM);
    cudaFuncSetAttribute(node_gemm, cudaFuncAttributeMaxDynamicSharedMemorySize,
                         NG_SMEM);
    cudaFuncSetAttribute(node_hid, cudaFuncAttributeMaxDynamicSharedMemorySize,
                         NH_SMEM);

    prep_gemm<<<D, D>>>(We2, be2, Wc1, bc1, Wn1);
    pack_all<<<96, 256>>>(We1, Wn1, Wn2);

    init_kernel<<<1184, 256>>>(coords, out_coords, N);

    int nblocks = (N + NT - 1) / NT;
    node_gemm<<<nblocks, NTHREADS, NG_SMEM>>>(h, be1, nullptr, 0, N);
    node_gemm<<<nblocks, NTHREADS, NG_SMEM>>>(h, be1, nullptr, 1, N);
    node_gemm<<<nblocks, NTHREADS, NG_SMEM>>>(h, bn1, nullptr, 2, N);

    edge_kernel<<<(E + ETILE - 1) / ETILE, NTHREADS, EDGE_SMEM>>>(
        coords, ei, We1, Wc2, out_coords, E);

    node_hid<<<nblocks, NTHREADS, NH_SMEM>>>(N);
    node_gemm<<<nblocks, NTHREADS, NG_SMEM>>>(h, bn2, out_h, 3, N);
}

// round 15
// speedup vs baseline: 1.0923x; 1.0923x over previous
#include <cuda_runtime.h>
#include <cuda_bf16.h>
#include <cstdint>

#define D 128
#define NTHREADS 256
#define MAXN 50000
#define ETILE 64
#define NT 64
#define A_STRIDE 136

// ---------------------------------------------------------------------------
// static scratch
// ---------------------------------------------------------------------------
__device__ float g_P1[(size_t)MAXN * D];   // h @ We1[0:128] + be1
__device__ float g_P2[(size_t)MAXN * D];   // h @ We1[128:256]
__device__ float g_Q1[(size_t)MAXN * D];   // h @ Wn1[0:128] + bn1
__device__ float g_agg[(size_t)MAXN * D];  // sum of hid per node
__device__ float g_deg[MAXN];              // degree (as float)
__device__ float g_bf[D];                  // be2 @ Wc1 + bc1
__device__ float g_bb[D];                  // be2 @ Wn1b
__device__ float g_Wf[D * D];              // We2 @ Wc1   (k-major)
__device__ float g_Wfn[D * D];             // We2 @ Wn1b  (k-major)
// B fragments in mma order: [hi/lo][nb(8)][ks(8)][lane(32)][4] u32 each
__device__ uint32_t g_frag_Wf[2 * 8 * 8 * 32 * 4];
__device__ uint32_t g_frag_Wfn[2 * 8 * 8 * 32 * 4];
__device__ uint32_t g_frag_E1a[2 * 8 * 8 * 32 * 4];
__device__ uint32_t g_frag_E1b[2 * 8 * 8 * 32 * 4];
__device__ uint32_t g_frag_N1a[2 * 8 * 8 * 32 * 4];
__device__ uint32_t g_frag_N2[2 * 8 * 8 * 32 * 4];

__device__ __forceinline__ float frelu(float x) { return x > 0.f ? x : 0.f; }

__device__ __forceinline__ uint32_t smem_u32(const void* p) {
    uint32_t a;
    asm("{ .reg .u64 t; cvta.to.shared.u64 t, %1; cvt.u32.u64 %0, t; }"
        : "=r"(a) : "l"(p));
    return a;
}

__device__ __forceinline__ void ldmat_x4(uint32_t& a0, uint32_t& a1,
                                         uint32_t& a2, uint32_t& a3,
                                         uint32_t addr) {
    asm volatile(
        "ldmatrix.sync.aligned.m8n8.x4.shared.b16 {%0,%1,%2,%3}, [%4];"
        : "=r"(a0), "=r"(a1), "=r"(a2), "=r"(a3) : "r"(addr));
}

__device__ __forceinline__ void mma_bf16(float d[4], uint32_t a0, uint32_t a1,
                                         uint32_t a2, uint32_t a3,
                                         uint32_t b0, uint32_t b1) {
    asm volatile(
        "mma.sync.aligned.m16n8k16.row.col.f32.bf16.bf16.f32 "
        "{%0,%1,%2,%3}, {%4,%5,%6,%7}, {%8,%9}, {%0,%1,%2,%3};"
        : "+f"(d[0]), "+f"(d[1]), "+f"(d[2]), "+f"(d[3])
        : "r"(a0), "r"(a1), "r"(a2), "r"(a3), "r"(b0), "r"(b1));
}

__device__ __forceinline__ void red_v4(float* dst, float4 v) {
    asm volatile(
        "red.global.add.v4.f32 [%0], {%1, %2, %3, %4};"
        :: "l"(dst), "f"(v.x), "f"(v.y), "f"(v.z), "f"(v.w) : "memory");
}

// ---------------------------------------------------------------------------
// 3-pass bf16x3 GEMM as a MACRO. Needs in scope: wid, lane, arow, acol8.
// ---------------------------------------------------------------------------
#define RUN_GEMM3(FRAG, AHI, ALO, DACC)                                        \
    do {                                                                       \
        _Pragma("unroll") for (int mt = 0; mt < 4; ++mt)                       \
            _Pragma("unroll") for (int nt = 0; nt < 2; ++nt)                   \
                _Pragma("unroll") for (int i = 0; i < 4; ++i)                  \
                    DACC[mt][nt][i] = 0.f;                                     \
        _Pragma("unroll") for (int pass = 0; pass < 3; ++pass) {               \
            const uint32_t abase_ = (pass == 1) ? (ALO) : (AHI);               \
            const int psel_ = (pass == 2) ? 1 : 0;                             \
            _Pragma("unroll") for (int ks = 0; ks < 8; ++ks) {                 \
                uint4 bv_ = *reinterpret_cast<const uint4*>(                   \
                    (FRAG) +                                                   \
                    ((((size_t)psel_ * 8 + wid) * 8 + ks) * 32 + lane) * 4);   \
                _Pragma("unroll") for (int mt = 0; mt < 4; ++mt) {             \
                    uint32_t addr_ = abase_ +                                  \
                        (uint32_t)((mt * 16 + arow) * (A_STRIDE * 2) +         \
                                   (ks * 16 + acol8) * 2);                     \
                    uint32_t a0_, a1_, a2_, a3_;                               \
                    ldmat_x4(a0_, a1_, a2_, a3_, addr_);                       \
                    mma_bf16(DACC[mt][0], a0_, a1_, a2_, a3_, bv_.x, bv_.y);   \
                    mma_bf16(DACC[mt][1], a0_, a1_, a2_, a3_, bv_.z, bv_.w);   \
                }                                                              \
            }                                                                  \
        }                                                                      \
    } while (0)

// store DACC (+ optional bias) to row-major fp32 out. Needs rb, nb, g, t, N.
#define STORE_OUT(OUT, BIAS, HASB, DACC)                                       \
    do {                                                                       \
        _Pragma("unroll") for (int mt = 0; mt < 4; ++mt) {                     \
            _Pragma("unroll") for (int nt = 0; nt < 2; ++nt) {                 \
                int c_ = nb + nt * 8 + t * 2;                                  \
                float b0_ = 0.f, b1_ = 0.f;                                    \
                if (HASB) {                                                    \
                    b0_ = __ldg((BIAS) + c_);                                  \
                    b1_ = __ldg((BIAS) + c_ + 1);                              \
                }                                                              \
                int r0_ = rb + mt * 16 + g;                                    \
                int r1_ = r0_ + 8;                                             \
                if (r0_ < N)                                                   \
                    *reinterpret_cast<float2*>((OUT) + (size_t)r0_ * D + c_) = \
                        make_float2(DACC[mt][nt][0] + b0_,                     \
                                    DACC[mt][nt][1] + b1_);                    \
                if (r1_ < N)                                                   \
                    *reinterpret_cast<float2*>((OUT) + (size_t)r1_ * D + c_) = \
                        make_float2(DACC[mt][nt][2] + b0_,                     \
                                    DACC[mt][nt][3] + b1_);                    \
            }                                                                  \
        }                                                                      \
    } while (0)

// ---------------------------------------------------------------------------
// prep_gemm: Wf = We2 @ Wc1, Wfn = We2 @ Wn1b (k-major fp32), bf, bb
// ---------------------------------------------------------------------------
__global__ void prep_gemm(const float* __restrict__ We2,
                          const float* __restrict__ be2,
                          const float* __restrict__ Wc1,
                          const float* __restrict__ bc1,
                          const float* __restrict__ Wn1) {
    int k = blockIdx.x;
    int j = threadIdx.x;
    const float* Wn1b = Wn1 + (size_t)128 * D;
    float a1 = 0.f, a2 = 0.f;
#pragma unroll 4
    for (int i = 0; i < D; ++i) {
        float w = We2[k * D + i];
        a1 += w * Wc1[i * D + j];
        a2 += w * Wn1b[i * D + j];
    }
    g_Wf[k * D + j] = a1;
    g_Wfn[k * D + j] = a2;
    if (k == 0) {
        float b1 = bc1[j], b2 = 0.f;
#pragma unroll 4
        for (int i = 0; i < D; ++i) {
            float b = be2[i];
            b1 += b * Wc1[i * D + j];
            b2 += b * Wn1b[i * D + j];
        }
        g_bf[j] = b1;
        g_bb[j] = b2;
    }
}

// ---------------------------------------------------------------------------
// pack_all: 6 weight matrices -> bf16 hi/lo mma B-fragments (device symbols)
// ---------------------------------------------------------------------------
__device__ __forceinline__ uint32_t wbits(const float* __restrict__ W, int c,
                                          int r, int p) {
    float v = W[c * D + r];
    __nv_bfloat16 hi = __float2bfloat16(v);
    if (p) {
        __nv_bfloat16 lo = __float2bfloat16(v - __bfloat162float(hi));
        return (uint32_t)__bfloat16_as_ushort(lo);
    }
    return (uint32_t)__bfloat16_as_ushort(hi);
}

__global__ void pack_all(const float* __restrict__ We1,
                         const float* __restrict__ Wn1,
                         const float* __restrict__ Wn2) {
    int gidx = blockIdx.x * blockDim.x + threadIdx.x;
    int m = gidx >> 12;
    int idx = gidx & 4095;
    const float* W;
    uint32_t* dst;
    switch (m) {
        case 0: W = g_Wf; dst = g_frag_Wf; break;
        case 1: W = g_Wfn; dst = g_frag_Wfn; break;
        case 2: W = We1; dst = g_frag_E1a; break;
        case 3: W = We1 + (size_t)128 * D; dst = g_frag_E1b; break;
        case 4: W = Wn1; dst = g_frag_N1a; break;
        default: W = Wn2; dst = g_frag_N2; break;
    }
    int lane = idx & 31;
    int ks = (idx >> 5) & 7;
    int nbk = (idx >> 8) & 7;
    int p = idx >> 11;
    int g = lane >> 2, t = lane & 3;
    int col = ks * 16 + t * 2;
    int r0 = nbk * 16 + g, r1 = r0 + 8;
    uint32_t* d = dst + (size_t)idx * 4;
    d[0] = wbits(W, col, r0, p) | (wbits(W, col + 1, r0, p) << 16);
    d[1] = wbits(W, col + 8, r0, p) | (wbits(W, col + 9, r0, p) << 16);
    d[2] = wbits(W, col, r1, p) | (wbits(W, col + 1, r1, p) << 16);
    d[3] = wbits(W, col + 8, r1, p) | (wbits(W, col + 9, r1, p) << 16);
}

// ---------------------------------------------------------------------------
// init
// ---------------------------------------------------------------------------
__global__ void init_kernel(const float* __restrict__ coords,
                            float* __restrict__ out_coords, int N) {
    int total4 = N * (D / 4);
    for (int i = blockIdx.x * blockDim.x + threadIdx.x; i < total4;
         i += gridDim.x * blockDim.x)
        reinterpret_cast<float4*>(g_agg)[i] = make_float4(0.f, 0.f, 0.f, 0.f);
    for (int i = blockIdx.x * blockDim.x + threadIdx.x; i < N;
         i += gridDim.x * blockDim.x)
        g_deg[i] = 0.f;
    int c3 = N * 3;
    for (int i = blockIdx.x * blockDim.x + threadIdx.x; i < c3;
         i += gridDim.x * blockDim.x)
        out_coords[i] = coords[i];
}

// ---------------------------------------------------------------------------
// node_prep_mma: P1 = h@We1a + be1 ; P2 = h@We1b ; Q1 = h@Wn1a + bn1
// Fused (stages h ONCE for 3 GEMMs) + (256,2) cap — cap proven spill-safe on
// the macro bodies by R14's node_gemm (128 regs, no violation).
// ---------------------------------------------------------------------------
#define NP_OFF_ALO 17408
#define NP_SMEM 34816

__global__ void __launch_bounds__(NTHREADS, 2)
node_prep_mma(const float* __restrict__ h,
              const float* __restrict__ be1,
              const float* __restrict__ bn1, int N) {
    extern __shared__ char sm[];
    const uint32_t sbase = smem_u32(sm);
    const int tid = threadIdx.x;
    const int rb = blockIdx.x * NT;

    for (int idx = tid; idx < NT * 32; idx += NTHREADS) {
        int e = idx >> 5, k4 = idx & 31;
        int row = rb + e;
        float4 hv = make_float4(0.f, 0.f, 0.f, 0.f);
        if (row < N)
            hv = *reinterpret_cast<const float4*>(h + (size_t)row * D + k4 * 4);
        __nv_bfloat162 hp0, hp1, lp0, lp1;
        hp0.x = __float2bfloat16(hv.x);
        hp0.y = __float2bfloat16(hv.y);
        hp1.x = __float2bfloat16(hv.z);
        hp1.y = __float2bfloat16(hv.w);
        lp0.x = __float2bfloat16(hv.x - __bfloat162float(hp0.x));
        lp0.y = __float2bfloat16(hv.y - __bfloat162float(hp0.y));
        lp1.x = __float2bfloat16(hv.z - __bfloat162float(hp1.x));
        lp1.y = __float2bfloat16(hv.w - __bfloat162float(hp1.y));
        size_t boff = ((size_t)e * A_STRIDE + k4 * 4) * 2;
        *reinterpret_cast<__nv_bfloat162*>(sm + boff) = hp0;
        *reinterpret_cast<__nv_bfloat162*>(sm + boff + 4) = hp1;
        *reinterpret_cast<__nv_bfloat162*>(sm + NP_OFF_ALO + boff) = lp0;
        *reinterpret_cast<__nv_bfloat162*>(sm + NP_OFF_ALO + boff + 4) = lp1;
    }
    __syncthreads();

    const int lane = tid & 31, wid = tid >> 5;
    const int g = lane >> 2, t = lane & 3;
    const int nb = wid * 16, arow = lane & 15, acol8 = (lane >> 4) * 8;
    const uint32_t ahi = sbase, alo = sbase + NP_OFF_ALO;

    {
        float dacc[4][2][4];
        RUN_GEMM3(g_frag_E1a, ahi, alo, dacc);
        STORE_OUT(g_P1, be1, true, dacc);
    }
    {
        float dacc[4][2][4];
        RUN_GEMM3(g_frag_E1b, ahi, alo, dacc);
        STORE_OUT(g_P2, be1, false, dacc);
    }
    {
        float dacc[4][2][4];
        RUN_GEMM3(g_frag_N1a, ahi, alo, dacc);
        STORE_OUT(g_Q1, bn1, true, dacc);
    }
}

// ---------------------------------------------------------------------------
// edge kernel (byte-for-byte R13 structure; proven 2 CTA/SM, no local mem)
// ---------------------------------------------------------------------------
#define OFF_AHI 0
#define OFF_ALO 17408
#define OFF_REL 34816
#define OFF_DIST 35840
#define OFF_W 36096
#define OFF_ROW 36352
#define OFF_COL 36608
#define EDGE_SMEM 36864

__global__ void __launch_bounds__(NTHREADS, 2)
edge_kernel(const float* __restrict__ coords,
            const int* __restrict__ ei,
            const float* __restrict__ We1,
            const float* __restrict__ Wc2,
            float* __restrict__ out_coords,
            int E) {
    extern __shared__ char sm[];
    float* s_rel = reinterpret_cast<float*>(sm + OFF_REL);
    float* s_dist = reinterpret_cast<float*>(sm + OFF_DIST);
    float* s_w = reinterpret_cast<float*>(sm + OFF_W);
    int* s_row = reinterpret_cast<int*>(sm + OFF_ROW);
    int* s_col = reinterpret_cast<int*>(sm + OFF_COL);

    const uint32_t sbase = smem_u32(sm);
    const int tid = threadIdx.x;
    const int e_base = blockIdx.x * ETILE;

    if (tid < ETILE) {
        int ge = e_base + tid;
        int r = 0, c = 0;
        if (ge < E) {
            r = ei[ge];
            c = ei[E + ge];
            atomicAdd(g_deg + r, 1.0f);
        }
        s_row[tid] = r;
        s_col[tid] = c;
        float rx = coords[r * 3 + 0] - coords[c * 3 + 0];
        float ry = coords[r * 3 + 1] - coords[c * 3 + 1];
        float rz = coords[r * 3 + 2] - coords[c * 3 + 2];
        s_rel[tid * 4 + 0] = rx;
        s_rel[tid * 4 + 1] = ry;
        s_rel[tid * 4 + 2] = rz;
        s_dist[tid] = rx * rx + ry * ry + rz * rz;
        s_w[tid] = 0.f;
    }
    __syncthreads();

    {
        const int k4 = tid & 31;
        float4 w4 = __ldg(reinterpret_cast<const float4*>(
            We1 + (size_t)256 * D + k4 * 4));
        for (int idx = tid; idx < ETILE * 32; idx += NTHREADS) {
            int e = idx >> 5;
            float4 hv = make_float4(0.f, 0.f, 0.f, 0.f);
            bool live = (e_base + e < E);
            if (live) {
                int r = s_row[e], c = s_col[e];
                float4 p1 = *reinterpret_cast<const float4*>(
                    g_P1 + (size_t)r * D + k4 * 4);
                float4 p2 = *reinterpret_cast<const float4*>(
                    g_P2 + (size_t)c * D + k4 * 4);
                float d2 = s_dist[e];
                hv.x = frelu(p1.x + p2.x + d2 * w4.x);
                hv.y = frelu(p1.y + p2.y + d2 * w4.y);
                hv.z = frelu(p1.z + p2.z + d2 * w4.z);
                hv.w = frelu(p1.w + p2.w + d2 * w4.w);
                red_v4(g_agg + (size_t)s_row[e] * D + k4 * 4, hv);
            }
            __nv_bfloat162 hp0, hp1, lp0, lp1;
            hp0.x = __float2bfloat16(hv.x);
            hp0.y = __float2bfloat16(hv.y);
            hp1.x = __float2bfloat16(hv.z);
            hp1.y = __float2bfloat16(hv.w);
            lp0.x = __float2bfloat16(hv.x - __bfloat162float(hp0.x));
            lp0.y = __float2bfloat16(hv.y - __bfloat162float(hp0.y));
            lp1.x = __float2bfloat16(hv.z - __bfloat162float(hp1.x));
            lp1.y = __float2bfloat16(hv.w - __bfloat162float(hp1.y));
            size_t boff = ((size_t)e * A_STRIDE + k4 * 4) * 2;
            *reinterpret_cast<__nv_bfloat162*>(sm + OFF_AHI + boff) = hp0;
            *reinterpret_cast<__nv_bfloat162*>(sm + OFF_AHI + boff + 4) = hp1;
            *reinterpret_cast<__nv_bfloat162*>(sm + OFF_ALO + boff) = lp0;
            *reinterpret_cast<__nv_bfloat162*>(sm + OFF_ALO + boff + 4) = lp1;
        }
    }
    __syncthreads();

    const int lane = tid & 31, wid = tid >> 5;
    const int g = lane >> 2, t = lane & 3;
    const int nb = wid * 16;
    const int arow = lane & 15;
    const int acol8 = (lane >> 4) * 8;

    float dacc[4][2][4];
    RUN_GEMM3(g_frag_Wf, sbase + OFF_AHI, sbase + OFF_ALO, dacc);

    {
        float p[4][2];
#pragma unroll
        for (int mt = 0; mt < 4; ++mt) p[mt][0] = p[mt][1] = 0.f;
#pragma unroll
        for (int nt = 0; nt < 2; ++nt) {
            int j = nb + nt * 8 + t * 2;
            float bf0 = __ldg(g_bf + j), bf1 = __ldg(g_bf + j + 1);
            float w0 = __ldg(Wc2 + j), w1 = __ldg(Wc2 + j + 1);
#pragma unroll
            for (int mt = 0; mt < 4; ++mt) {
                p[mt][0] += frelu(dacc[mt][nt][0] + bf0) * w0 +
                            frelu(dacc[mt][nt][1] + bf1) * w1;
                p[mt][1] += frelu(dacc[mt][nt][2] + bf0) * w0 +
                            frelu(dacc[mt][nt][3] + bf1) * w1;
            }
        }
#pragma unroll
        for (int off = 1; off <= 2; off <<= 1)
#pragma unroll
            for (int mt = 0; mt < 4; ++mt) {
                p[mt][0] += __shfl_xor_sync(0xffffffffu, p[mt][0], off);
                p[mt][1] += __shfl_xor_sync(0xffffffffu, p[mt][1], off);
            }
        if (t == 0) {
#pragma unroll
            for (int mt = 0; mt < 4; ++mt) {
                atomicAdd(s_w + mt * 16 + g, p[mt][0]);
                atomicAdd(s_w + mt * 16 + 8 + g, p[mt][1]);
            }
        }
    }
    __syncthreads();

    if (tid < ETILE) {
        int ge = e_base + tid;
        if (ge < E) {
            float w = s_w[tid];
            int r = s_row[tid];
            atomicAdd(out_coords + r * 3 + 0, w * s_rel[tid * 4 + 0]);
            atomicAdd(out_coords + r * 3 + 1, w * s_rel[tid * 4 + 1]);
            atomicAdd(out_coords + r * 3 + 2, w * s_rel[tid * 4 + 2]);
        }
    }
}

// ---------------------------------------------------------------------------
// node_mma: hid = relu(Q1 + agg @ Wfn + deg*bb) ; out = hid @ Wn2 + bn2
// Fused with in-place smem repack (no global hid round trip) + (256,2) cap.
// ---------------------------------------------------------------------------
#define NK_OFF_ALO 17408
#define NK_OFF_DEG 34816
#define NK_SMEM 35072

__global__ void __launch_bounds__(NTHREADS, 2)
node_mma(const float* __restrict__ bn2, float* __restrict__ out_h, int N) {
    extern __shared__ char sm[];
    float* s_deg = reinterpret_cast<float*>(sm + NK_OFF_DEG);
    const uint32_t sbase = smem_u32(sm);
    const int tid = threadIdx.x;
    const int rb = blockIdx.x * NT;

    for (int idx = tid; idx < NT * 32; idx += NTHREADS) {
        int e = idx >> 5, k4 = idx & 31;
        int row = rb + e;
        float4 av = make_float4(0.f, 0.f, 0.f, 0.f);
        if (row < N)
            av = *reinterpret_cast<const float4*>(g_agg + (size_t)row * D + k4 * 4);
        __nv_bfloat162 hp0, hp1, lp0, lp1;
        hp0.x = __float2bfloat16(av.x);
        hp0.y = __float2bfloat16(av.y);
        hp1.x = __float2bfloat16(av.z);
        hp1.y = __float2bfloat16(av.w);
        lp0.x = __float2bfloat16(av.x - __bfloat162float(hp0.x));
        lp0.y = __float2bfloat16(av.y - __bfloat162float(hp0.y));
        lp1.x = __float2bfloat16(av.z - __bfloat162float(hp1.x));
        lp1.y = __float2bfloat16(av.w - __bfloat162float(hp1.y));
        size_t boff = ((size_t)e * A_STRIDE + k4 * 4) * 2;
        *reinterpret_cast<__nv_bfloat162*>(sm + boff) = hp0;
        *reinterpret_cast<__nv_bfloat162*>(sm + boff + 4) = hp1;
        *reinterpret_cast<__nv_bfloat162*>(sm + NK_OFF_ALO + boff) = lp0;
        *reinterpret_cast<__nv_bfloat162*>(sm + NK_OFF_ALO + boff + 4) = lp1;
    }
    if (tid < NT) {
        int row = rb + tid;
        s_deg[tid] = (row < N) ? g_deg[row] : 0.f;
    }
    __syncthreads();

    const int lane = tid & 31, wid = tid >> 5;
    const int g = lane >> 2, t = lane & 3;
    const int nb = wid * 16, arow = lane & 15, acol8 = (lane >> 4) * 8;
    const uint32_t ahi = sbase, alo = sbase + NK_OFF_ALO;

    float dacc[4][2][4];
    RUN_GEMM3(g_frag_Wfn, ahi, alo, dacc);

    __syncthreads();  // all GEMM1 A-tile reads complete before overwrite

    // hid = relu(Q1 + z + deg*bb) -> overwrite A tiles in place
#pragma unroll
    for (int mt = 0; mt < 4; ++mt) {
        float d0 = s_deg[mt * 16 + g];
        float d1 = s_deg[mt * 16 + g + 8];
        int r0 = rb + mt * 16 + g, r1 = r0 + 8;
        int rl0 = mt * 16 + g, rl1 = rl0 + 8;
#pragma unroll
        for (int nt = 0; nt < 2; ++nt) {
            int c = nb + nt * 8 + t * 2;
            float2 bb = *reinterpret_cast<const float2*>(g_bb + c);
            float q00 = 0.f, q01 = 0.f, q10 = 0.f, q11 = 0.f;
            if (r0 < N) {
                float2 q = *reinterpret_cast<const float2*>(g_Q1 + (size_t)r0 * D + c);
                q00 = q.x; q01 = q.y;
            }
            if (r1 < N) {
                float2 q = *reinterpret_cast<const float2*>(g_Q1 + (size_t)r1 * D + c);
                q10 = q.x; q11 = q.y;
            }
            float h00 = frelu(dacc[mt][nt][0] + q00 + d0 * bb.x);
            float h01 = frelu(dacc[mt][nt][1] + q01 + d0 * bb.y);
            float h10 = frelu(dacc[mt][nt][2] + q10 + d1 * bb.x);
            float h11 = frelu(dacc[mt][nt][3] + q11 + d1 * bb.y);
            __nv_bfloat162 ph0, pl0, ph1, pl1;
            ph0.x = __float2bfloat16(h00);
            ph0.y = __float2bfloat16(h01);
            pl0.x = __float2bfloat16(h00 - __bfloat162float(ph0.x));
            pl0.y = __float2bfloat16(h01 - __bfloat162float(ph0.y));
            ph1.x = __float2bfloat16(h10);
            ph1.y = __float2bfloat16(h11);
            pl1.x = __float2bfloat16(h10 - __bfloat162float(ph1.x));
            pl1.y = __float2bfloat16(h11 - __bfloat162float(ph1.y));
            size_t o0 = ((size_t)rl0 * A_STRIDE + c) * 2;
            size_t o1 = ((size_t)rl1 * A_STRIDE + c) * 2;
            *reinterpret_cast<__nv_bfloat162*>(sm + o0) = ph0;
            *reinterpret_cast<__nv_bfloat162*>(sm + NK_OFF_ALO + o0) = pl0;
            *reinterpret_cast<__nv_bfloat162*>(sm + o1) = ph1;
            *reinterpret_cast<__nv_bfloat162*>(sm + NK_OFF_ALO + o1) = pl1;
        }
    }
    __syncthreads();

    RUN_GEMM3(g_frag_N2, ahi, alo, dacc);
    STORE_OUT(out_h, bn2, true, dacc);
}

// ---------------------------------------------------------------------------
// launch
// ---------------------------------------------------------------------------
extern "C" void kernel_launch(void* const* d_in, const int* in_sizes, int n_in,
                              void* d_out, int out_size) {
    const float* h = (const float*)d_in[0];
    const float* coords = (const float*)d_in[1];
    const int* ei = (const int*)d_in[2];
    const float* We1 = (const float*)d_in[3];
    const float* be1 = (const float*)d_in[4];
    const float* We2 = (const float*)d_in[5];
    const float* be2 = (const float*)d_in[6];
    const float* Wn1 = (const float*)d_in[7];
    const float* bn1 = (const float*)d_in[8];
    const float* Wn2 = (const float*)d_in[9];
    const float* bn2 = (const float*)d_in[10];
    const float* Wc1 = (const float*)d_in[11];
    const float* bc1 = (const float*)d_in[12];
    const float* Wc2 = (const float*)d_in[13];

    int N = in_sizes[0] / D;
    int E = in_sizes[2] / 2;

    float* out_h = (float*)d_out;
    float* out_coords = out_h + (size_t)N * D;

    cudaFuncSetAttribute(edge_kernel, cudaFuncAttributeMaxDynamicSharedMemorySize,
                         EDGE_SMEM);
    cudaFuncSetAttribute(node_prep_mma, cudaFuncAttributeMaxDynamicSharedMemorySize,
                         NP_SMEM);
    cudaFuncSetAttribute(node_mma, cudaFuncAttributeMaxDynamicSharedMemorySize,
                         NK_SMEM);

    prep_gemm<<<D, D>>>(We2, be2, Wc1, bc1, Wn1);
    pack_all<<<96, 256>>>(We1, Wn1, Wn2);

    init_kernel<<<1184, 256>>>(coords, out_coords, N);

    int nblocks = (N + NT - 1) / NT;
    node_prep_mma<<<nblocks, NTHREADS, NP_SMEM>>>(h, be1, bn1, N);

    edge_kernel<<<(E + ETILE - 1) / ETILE, NTHREADS, EDGE_SMEM>>>(
        coords, ei, We1, Wc2, out_coords, E);

    node_mma<<<nblocks, NTHREADS, NK_SMEM>>>(bn2, out_h, N);
}

// round 16
// speedup vs baseline: 1.3404x; 1.2271x over previous
#include <cuda_runtime.h>
#include <cuda_bf16.h>
#include <cstdint>

#define D 128
#define NTHREADS 256
#define MAXN 50000
#define ETILE 64
#define NT 64
#define A_STRIDE 136

// ---------------------------------------------------------------------------
// static scratch
// ---------------------------------------------------------------------------
__device__ float g_P1[(size_t)MAXN * D];   // h @ We1[0:128] + be1
__device__ float g_P2[(size_t)MAXN * D];   // h @ We1[128:256]
__device__ float g_Q1[(size_t)MAXN * D];   // h @ Wn1[0:128] + bn1
__device__ float g_agg[(size_t)MAXN * D];  // sum of hid per node
__device__ float g_deg[MAXN];              // degree (as float)
__device__ float g_bf[D];                  // be2 @ Wc1 + bc1
__device__ float g_bb[D];                  // be2 @ Wn1b
__device__ float g_Wf[D * D];              // We2 @ Wc1   (k-major)
__device__ float g_Wfn[D * D];             // We2 @ Wn1b  (k-major)
// B fragments in mma order: [hi/lo][nb(8)][ks(8)][lane(32)][4] u32 each
__device__ uint32_t g_frag_Wf[2 * 8 * 8 * 32 * 4];
__device__ uint32_t g_frag_Wfn[2 * 8 * 8 * 32 * 4];
__device__ uint32_t g_frag_E1a[2 * 8 * 8 * 32 * 4];
__device__ uint32_t g_frag_E1b[2 * 8 * 8 * 32 * 4];
__device__ uint32_t g_frag_N1a[2 * 8 * 8 * 32 * 4];
__device__ uint32_t g_frag_N2[2 * 8 * 8 * 32 * 4];

__device__ __forceinline__ float frelu(float x) { return x > 0.f ? x : 0.f; }

__device__ __forceinline__ uint32_t smem_u32(const void* p) {
    uint32_t a;
    asm("{ .reg .u64 t; cvta.to.shared.u64 t, %1; cvt.u32.u64 %0, t; }"
        : "=r"(a) : "l"(p));
    return a;
}

__device__ __forceinline__ void ldmat_x4(uint32_t& a0, uint32_t& a1,
                                         uint32_t& a2, uint32_t& a3,
                                         uint32_t addr) {
    asm volatile(
        "ldmatrix.sync.aligned.m8n8.x4.shared.b16 {%0,%1,%2,%3}, [%4];"
        : "=r"(a0), "=r"(a1), "=r"(a2), "=r"(a3) : "r"(addr));
}

__device__ __forceinline__ void mma_bf16(float d[4], uint32_t a0, uint32_t a1,
                                         uint32_t a2, uint32_t a3,
                                         uint32_t b0, uint32_t b1) {
    asm volatile(
        "mma.sync.aligned.m16n8k16.row.col.f32.bf16.bf16.f32 "
        "{%0,%1,%2,%3}, {%4,%5,%6,%7}, {%8,%9}, {%0,%1,%2,%3};"
        : "+f"(d[0]), "+f"(d[1]), "+f"(d[2]), "+f"(d[3])
        : "r"(a0), "r"(a1), "r"(a2), "r"(a3), "r"(b0), "r"(b1));
}

__device__ __forceinline__ void red_v4(float* dst, float4 v) {
    asm volatile(
        "red.global.add.v4.f32 [%0], {%1, %2, %3, %4};"
        :: "l"(dst), "f"(v.x), "f"(v.y), "f"(v.z), "f"(v.w) : "memory");
}

// ---------------------------------------------------------------------------
// 3-term bf16 split GEMM, ks-OUTER restructure: per ks load bhi+blo once,
// per (ks,mt) load ahi+alo once, issue all 6 MMAs. Same terms as the old
// 3-pass loop (identical numerics); ldmatrix 96->64, B LDG 24->16 per warp.
// Needs in scope: wid, lane, arow, acol8. DACC: float [4][2][4].
// ---------------------------------------------------------------------------
#define RUN_GEMM3(FRAG, AHI, ALO, DACC)                                        \
    do {                                                                       \
        _Pragma("unroll") for (int mt = 0; mt < 4; ++mt)                       \
            _Pragma("unroll") for (int nt = 0; nt < 2; ++nt)                   \
                _Pragma("unroll") for (int i = 0; i < 4; ++i)                  \
                    DACC[mt][nt][i] = 0.f;                                     \
        _Pragma("unroll") for (int ks = 0; ks < 8; ++ks) {                     \
            uint4 bh_ = *reinterpret_cast<const uint4*>(                       \
                (FRAG) + (((size_t)wid * 8 + ks) * 32 + lane) * 4);            \
            uint4 bl_ = *reinterpret_cast<const uint4*>(                       \
                (FRAG) + ((((size_t)8 + wid) * 8 + ks) * 32 + lane) * 4);      \
            _Pragma("unroll") for (int mt = 0; mt < 4; ++mt) {                 \
                uint32_t aoff_ =                                               \
                    (uint32_t)((mt * 16 + arow) * (A_STRIDE * 2) +             \
                               (ks * 16 + acol8) * 2);                         \
                uint32_t h0_, h1_, h2_, h3_, l0_, l1_, l2_, l3_;               \
                ldmat_x4(h0_, h1_, h2_, h3_, (AHI) + aoff_);                   \
                ldmat_x4(l0_, l1_, l2_, l3_, (ALO) + aoff_);                   \
                mma_bf16(DACC[mt][0], h0_, h1_, h2_, h3_, bh_.x, bh_.y);       \
                mma_bf16(DACC[mt][1], h0_, h1_, h2_, h3_, bh_.z, bh_.w);       \
                mma_bf16(DACC[mt][0], l0_, l1_, l2_, l3_, bh_.x, bh_.y);       \
                mma_bf16(DACC[mt][1], l0_, l1_, l2_, l3_, bh_.z, bh_.w);       \
                mma_bf16(DACC[mt][0], h0_, h1_, h2_, h3_, bl_.x, bl_.y);       \
                mma_bf16(DACC[mt][1], h0_, h1_, h2_, h3_, bl_.z, bl_.w);       \
            }                                                                  \
        }                                                                      \
    } while (0)

// store DACC (+ optional bias) to row-major fp32 out. Needs rb, nb, g, t, N.
#define STORE_OUT(OUT, BIAS, HASB, DACC)                                       \
    do {                                                                       \
        _Pragma("unroll") for (int mt = 0; mt < 4; ++mt) {                     \
            _Pragma("unroll") for (int nt = 0; nt < 2; ++nt) {                 \
                int c_ = nb + nt * 8 + t * 2;                                  \
                float b0_ = 0.f, b1_ = 0.f;                                    \
                if (HASB) {                                                    \
                    b0_ = __ldg((BIAS) + c_);                                  \
                    b1_ = __ldg((BIAS) + c_ + 1);                              \
                }                                                              \
                int r0_ = rb + mt * 16 + g;                                    \
                int r1_ = r0_ + 8;                                             \
                if (r0_ < N)                                                   \
                    *reinterpret_cast<float2*>((OUT) + (size_t)r0_ * D + c_) = \
                        make_float2(DACC[mt][nt][0] + b0_,                     \
                                    DACC[mt][nt][1] + b1_);                    \
                if (r1_ < N)                                                   \
                    *reinterpret_cast<float2*>((OUT) + (size_t)r1_ * D + c_) = \
                        make_float2(DACC[mt][nt][2] + b0_,                     \
                                    DACC[mt][nt][3] + b1_);                    \
            }                                                                  \
        }                                                                      \
    } while (0)

// ---------------------------------------------------------------------------
// prep_gemm: Wf = We2 @ Wc1, Wfn = We2 @ Wn1b (k-major fp32), bf, bb
// ---------------------------------------------------------------------------
__global__ void prep_gemm(const float* __restrict__ We2,
                          const float* __restrict__ be2,
                          const float* __restrict__ Wc1,
                          const float* __restrict__ bc1,
                          const float* __restrict__ Wn1) {
    int k = blockIdx.x;
    int j = threadIdx.x;
    const float* Wn1b = Wn1 + (size_t)128 * D;
    float a1 = 0.f, a2 = 0.f;
#pragma unroll 4
    for (int i = 0; i < D; ++i) {
        float w = We2[k * D + i];
        a1 += w * Wc1[i * D + j];
        a2 += w * Wn1b[i * D + j];
    }
    g_Wf[k * D + j] = a1;
    g_Wfn[k * D + j] = a2;
    if (k == 0) {
        float b1 = bc1[j], b2 = 0.f;
#pragma unroll 4
        for (int i = 0; i < D; ++i) {
            float b = be2[i];
            b1 += b * Wc1[i * D + j];
            b2 += b * Wn1b[i * D + j];
        }
        g_bf[j] = b1;
        g_bb[j] = b2;
    }
}

// ---------------------------------------------------------------------------
// pack_all: 6 weight matrices -> bf16 hi/lo mma B-fragments (device symbols)
// ---------------------------------------------------------------------------
__device__ __forceinline__ uint32_t wbits(const float* __restrict__ W, int c,
                                          int r, int p) {
    float v = W[c * D + r];
    __nv_bfloat16 hi = __float2bfloat16(v);
    if (p) {
        __nv_bfloat16 lo = __float2bfloat16(v - __bfloat162float(hi));
        return (uint32_t)__bfloat16_as_ushort(lo);
    }
    return (uint32_t)__bfloat16_as_ushort(hi);
}

__global__ void pack_all(const float* __restrict__ We1,
                         const float* __restrict__ Wn1,
                         const float* __restrict__ Wn2) {
    int gidx = blockIdx.x * blockDim.x + threadIdx.x;
    int m = gidx >> 12;
    int idx = gidx & 4095;
    const float* W;
    uint32_t* dst;
    switch (m) {
        case 0: W = g_Wf; dst = g_frag_Wf; break;
        case 1: W = g_Wfn; dst = g_frag_Wfn; break;
        case 2: W = We1; dst = g_frag_E1a; break;
        case 3: W = We1 + (size_t)128 * D; dst = g_frag_E1b; break;
        case 4: W = Wn1; dst = g_frag_N1a; break;
        default: W = Wn2; dst = g_frag_N2; break;
    }
    int lane = idx & 31;
    int ks = (idx >> 5) & 7;
    int nbk = (idx >> 8) & 7;
    int p = idx >> 11;
    int g = lane >> 2, t = lane & 3;
    int col = ks * 16 + t * 2;
    int r0 = nbk * 16 + g, r1 = r0 + 8;
    uint32_t* d = dst + (size_t)idx * 4;
    d[0] = wbits(W, col, r0, p) | (wbits(W, col + 1, r0, p) << 16);
    d[1] = wbits(W, col + 8, r0, p) | (wbits(W, col + 9, r0, p) << 16);
    d[2] = wbits(W, col, r1, p) | (wbits(W, col + 1, r1, p) << 16);
    d[3] = wbits(W, col + 8, r1, p) | (wbits(W, col + 9, r1, p) << 16);
}

// ---------------------------------------------------------------------------
// init
// ---------------------------------------------------------------------------
__global__ void init_kernel(const float* __restrict__ coords,
                            float* __restrict__ out_coords, int N) {
    int total4 = N * (D / 4);
    for (int i = blockIdx.x * blockDim.x + threadIdx.x; i < total4;
         i += gridDim.x * blockDim.x)
        reinterpret_cast<float4*>(g_agg)[i] = make_float4(0.f, 0.f, 0.f, 0.f);
    for (int i = blockIdx.x * blockDim.x + threadIdx.x; i < N;
         i += gridDim.x * blockDim.x)
        g_deg[i] = 0.f;
    int c3 = N * 3;
    for (int i = blockIdx.x * blockDim.x + threadIdx.x; i < c3;
         i += gridDim.x * blockDim.x)
        out_coords[i] = coords[i];
}

// ---------------------------------------------------------------------------
// node_prep_mma: P1 = h@We1a + be1 ; P2 = h@We1b ; Q1 = h@Wn1a + bn1
// Uncapped (R13-proven; cap showed zero benefit in R15).
// ---------------------------------------------------------------------------
#define NP_OFF_ALO 17408
#define NP_SMEM 34816

__global__ void __launch_bounds__(NTHREADS)
node_prep_mma(const float* __restrict__ h,
              const float* __restrict__ be1,
              const float* __restrict__ bn1, int N) {
    extern __shared__ char sm[];
    const uint32_t sbase = smem_u32(sm);
    const int tid = threadIdx.x;
    const int rb = blockIdx.x * NT;

    for (int idx = tid; idx < NT * 32; idx += NTHREADS) {
        int e = idx >> 5, k4 = idx & 31;
        int row = rb + e;
        float4 hv = make_float4(0.f, 0.f, 0.f, 0.f);
        if (row < N)
            hv = *reinterpret_cast<const float4*>(h + (size_t)row * D + k4 * 4);
        __nv_bfloat162 hp0, hp1, lp0, lp1;
        hp0.x = __float2bfloat16(hv.x);
        hp0.y = __float2bfloat16(hv.y);
        hp1.x = __float2bfloat16(hv.z);
        hp1.y = __float2bfloat16(hv.w);
        lp0.x = __float2bfloat16(hv.x - __bfloat162float(hp0.x));
        lp0.y = __float2bfloat16(hv.y - __bfloat162float(hp0.y));
        lp1.x = __float2bfloat16(hv.z - __bfloat162float(hp1.x));
        lp1.y = __float2bfloat16(hv.w - __bfloat162float(hp1.y));
        size_t boff = ((size_t)e * A_STRIDE + k4 * 4) * 2;
        *reinterpret_cast<__nv_bfloat162*>(sm + boff) = hp0;
        *reinterpret_cast<__nv_bfloat162*>(sm + boff + 4) = hp1;
        *reinterpret_cast<__nv_bfloat162*>(sm + NP_OFF_ALO + boff) = lp0;
        *reinterpret_cast<__nv_bfloat162*>(sm + NP_OFF_ALO + boff + 4) = lp1;
    }
    __syncthreads();

    const int lane = tid & 31, wid = tid >> 5;
    const int g = lane >> 2, t = lane & 3;
    const int nb = wid * 16, arow = lane & 15, acol8 = (lane >> 4) * 8;
    const uint32_t ahi = sbase, alo = sbase + NP_OFF_ALO;

    {
        float dacc[4][2][4];
        RUN_GEMM3(g_frag_E1a, ahi, alo, dacc);
        STORE_OUT(g_P1, be1, true, dacc);
    }
    {
        float dacc[4][2][4];
        RUN_GEMM3(g_frag_E1b, ahi, alo, dacc);
        STORE_OUT(g_P2, be1, false, dacc);
    }
    {
        float dacc[4][2][4];
        RUN_GEMM3(g_frag_N1a, ahi, alo, dacc);
        STORE_OUT(g_Q1, bn1, true, dacc);
    }
}

// ---------------------------------------------------------------------------
// edge kernel (R13 structure + restructured GEMM loop; (256,2) cap kept)
// ---------------------------------------------------------------------------
#define OFF_AHI 0
#define OFF_ALO 17408
#define OFF_REL 34816
#define OFF_DIST 35840
#define OFF_W 36096
#define OFF_ROW 36352
#define OFF_COL 36608
#define EDGE_SMEM 36864

__global__ void __launch_bounds__(NTHREADS, 2)
edge_kernel(const float* __restrict__ coords,
            const int* __restrict__ ei,
            const float* __restrict__ We1,
            const float* __restrict__ Wc2,
            float* __restrict__ out_coords,
            int E) {
    extern __shared__ char sm[];
    float* s_rel = reinterpret_cast<float*>(sm + OFF_REL);
    float* s_dist = reinterpret_cast<float*>(sm + OFF_DIST);
    float* s_w = reinterpret_cast<float*>(sm + OFF_W);
    int* s_row = reinterpret_cast<int*>(sm + OFF_ROW);
    int* s_col = reinterpret_cast<int*>(sm + OFF_COL);

    const uint32_t sbase = smem_u32(sm);
    const int tid = threadIdx.x;
    const int e_base = blockIdx.x * ETILE;

    if (tid < ETILE) {
        int ge = e_base + tid;
        int r = 0, c = 0;
        if (ge < E) {
            r = ei[ge];
            c = ei[E + ge];
            atomicAdd(g_deg + r, 1.0f);
        }
        s_row[tid] = r;
        s_col[tid] = c;
        float rx = coords[r * 3 + 0] - coords[c * 3 + 0];
        float ry = coords[r * 3 + 1] - coords[c * 3 + 1];
        float rz = coords[r * 3 + 2] - coords[c * 3 + 2];
        s_rel[tid * 4 + 0] = rx;
        s_rel[tid * 4 + 1] = ry;
        s_rel[tid * 4 + 2] = rz;
        s_dist[tid] = rx * rx + ry * ry + rz * rz;
        s_w[tid] = 0.f;
    }
    __syncthreads();

    {
        const int k4 = tid & 31;
        float4 w4 = __ldg(reinterpret_cast<const float4*>(
            We1 + (size_t)256 * D + k4 * 4));
        for (int idx = tid; idx < ETILE * 32; idx += NTHREADS) {
            int e = idx >> 5;
            float4 hv = make_float4(0.f, 0.f, 0.f, 0.f);
            bool live = (e_base + e < E);
            if (live) {
                int r = s_row[e], c = s_col[e];
                float4 p1 = *reinterpret_cast<const float4*>(
                    g_P1 + (size_t)r * D + k4 * 4);
                float4 p2 = *reinterpret_cast<const float4*>(
                    g_P2 + (size_t)c * D + k4 * 4);
                float d2 = s_dist[e];
                hv.x = frelu(p1.x + p2.x + d2 * w4.x);
                hv.y = frelu(p1.y + p2.y + d2 * w4.y);
                hv.z = frelu(p1.z + p2.z + d2 * w4.z);
                hv.w = frelu(p1.w + p2.w + d2 * w4.w);
                red_v4(g_agg + (size_t)s_row[e] * D + k4 * 4, hv);
            }
            __nv_bfloat162 hp0, hp1, lp0, lp1;
            hp0.x = __float2bfloat16(hv.x);
            hp0.y = __float2bfloat16(hv.y);
            hp1.x = __float2bfloat16(hv.z);
            hp1.y = __float2bfloat16(hv.w);
            lp0.x = __float2bfloat16(hv.x - __bfloat162float(hp0.x));
            lp0.y = __float2bfloat16(hv.y - __bfloat162float(hp0.y));
            lp1.x = __float2bfloat16(hv.z - __bfloat162float(hp1.x));
            lp1.y = __float2bfloat16(hv.w - __bfloat162float(hp1.y));
            size_t boff = ((size_t)e * A_STRIDE + k4 * 4) * 2;
            *reinterpret_cast<__nv_bfloat162*>(sm + OFF_AHI + boff) = hp0;
            *reinterpret_cast<__nv_bfloat162*>(sm + OFF_AHI + boff + 4) = hp1;
            *reinterpret_cast<__nv_bfloat162*>(sm + OFF_ALO + boff) = lp0;
            *reinterpret_cast<__nv_bfloat162*>(sm + OFF_ALO + boff + 4) = lp1;
        }
    }
    __syncthreads();

    const int lane = tid & 31, wid = tid >> 5;
    const int g = lane >> 2, t = lane & 3;
    const int nb = wid * 16;
    const int arow = lane & 15;
    const int acol8 = (lane >> 4) * 8;

    float dacc[4][2][4];
    RUN_GEMM3(g_frag_Wf, sbase + OFF_AHI, sbase + OFF_ALO, dacc);

    {
        float p[4][2];
#pragma unroll
        for (int mt = 0; mt < 4; ++mt) p[mt][0] = p[mt][1] = 0.f;
#pragma unroll
        for (int nt = 0; nt < 2; ++nt) {
            int j = nb + nt * 8 + t * 2;
            float bf0 = __ldg(g_bf + j), bf1 = __ldg(g_bf + j + 1);
            float w0 = __ldg(Wc2 + j), w1 = __ldg(Wc2 + j + 1);
#pragma unroll
            for (int mt = 0; mt < 4; ++mt) {
                p[mt][0] += frelu(dacc[mt][nt][0] + bf0) * w0 +
                            frelu(dacc[mt][nt][1] + bf1) * w1;
                p[mt][1] += frelu(dacc[mt][nt][2] + bf0) * w0 +
                            frelu(dacc[mt][nt][3] + bf1) * w1;
            }
        }
#pragma unroll
        for (int off = 1; off <= 2; off <<= 1)
#pragma unroll
            for (int mt = 0; mt < 4; ++mt) {
                p[mt][0] += __shfl_xor_sync(0xffffffffu, p[mt][0], off);
                p[mt][1] += __shfl_xor_sync(0xffffffffu, p[mt][1], off);
            }
        if (t == 0) {
#pragma unroll
            for (int mt = 0; mt < 4; ++mt) {
                atomicAdd(s_w + mt * 16 + g, p[mt][0]);
                atomicAdd(s_w + mt * 16 + 8 + g, p[mt][1]);
            }
        }
    }
    __syncthreads();

    if (tid < ETILE) {
        int ge = e_base + tid;
        if (ge < E) {
            float w = s_w[tid];
            int r = s_row[tid];
            atomicAdd(out_coords + r * 3 + 0, w * s_rel[tid * 4 + 0]);
            atomicAdd(out_coords + r * 3 + 1, w * s_rel[tid * 4 + 1]);
            atomicAdd(out_coords + r * 3 + 2, w * s_rel[tid * 4 + 2]);
        }
    }
}

// ---------------------------------------------------------------------------
// node_mma: hid = relu(Q1 + agg @ Wfn + deg*bb) ; out = hid @ Wn2 + bn2
// Uncapped (see node_prep_mma).
// ---------------------------------------------------------------------------
#define NK_OFF_ALO 17408
#define NK_OFF_DEG 34816
#define NK_SMEM 35072

__global__ void __launch_bounds__(NTHREADS)
node_mma(const float* __restrict__ bn2, float* __restrict__ out_h, int N) {
    extern __shared__ char sm[];
    float* s_deg = reinterpret_cast<float*>(sm + NK_OFF_DEG);
    const uint32_t sbase = smem_u32(sm);
    const int tid = threadIdx.x;
    const int rb = blockIdx.x * NT;

    for (int idx = tid; idx < NT * 32; idx += NTHREADS) {
        int e = idx >> 5, k4 = idx & 31;
        int row = rb + e;
        float4 av = make_float4(0.f, 0.f, 0.f, 0.f);
        if (row < N)
            av = *reinterpret_cast<const float4*>(g_agg + (size_t)row * D + k4 * 4);
        __nv_bfloat162 hp0, hp1, lp0, lp1;
        hp0.x = __float2bfloat16(av.x);
        hp0.y = __float2bfloat16(av.y);
        hp1.x = __float2bfloat16(av.z);
        hp1.y = __float2bfloat16(av.w);
        lp0.x = __float2bfloat16(av.x - __bfloat162float(hp0.x));
        lp0.y = __float2bfloat16(av.y - __bfloat162float(hp0.y));
        lp1.x = __float2bfloat16(av.z - __bfloat162float(hp1.x));
        lp1.y = __float2bfloat16(av.w - __bfloat162float(hp1.y));
        size_t boff = ((size_t)e * A_STRIDE + k4 * 4) * 2;
        *reinterpret_cast<__nv_bfloat162*>(sm + boff) = hp0;
        *reinterpret_cast<__nv_bfloat162*>(sm + boff + 4) = hp1;
        *reinterpret_cast<__nv_bfloat162*>(sm + NK_OFF_ALO + boff) = lp0;
        *reinterpret_cast<__nv_bfloat162*>(sm + NK_OFF_ALO + boff + 4) = lp1;
    }
    if (tid < NT) {
        int row = rb + tid;
        s_deg[tid] = (row < N) ? g_deg[row] : 0.f;
    }
    __syncthreads();

    const int lane = tid & 31, wid = tid >> 5;
    const int g = lane >> 2, t = lane & 3;
    const int nb = wid * 16, arow = lane & 15, acol8 = (lane >> 4) * 8;
    const uint32_t ahi = sbase, alo = sbase + NK_OFF_ALO;

    float dacc[4][2][4];
    RUN_GEMM3(g_frag_Wfn, ahi, alo, dacc);

    __syncthreads();  // all GEMM1 A-tile reads complete before overwrite

    // hid = relu(Q1 + z + deg*bb) -> overwrite A tiles in place
#pragma unroll
    for (int mt = 0; mt < 4; ++mt) {
        float d0 = s_deg[mt * 16 + g];
        float d1 = s_deg[mt * 16 + g + 8];
        int r0 = rb + mt * 16 + g, r1 = r0 + 8;
        int rl0 = mt * 16 + g, rl1 = rl0 + 8;
#pragma unroll
        for (int nt = 0; nt < 2; ++nt) {
            int c = nb + nt * 8 + t * 2;
            float2 bb = *reinterpret_cast<const float2*>(g_bb + c);
            float q00 = 0.f, q01 = 0.f, q10 = 0.f, q11 = 0.f;
            if (r0 < N) {
                float2 q = *reinterpret_cast<const float2*>(g_Q1 + (size_t)r0 * D + c);
                q00 = q.x; q01 = q.y;
            }
            if (r1 < N) {
                float2 q = *reinterpret_cast<const float2*>(g_Q1 + (size_t)r1 * D + c);
                q10 = q.x; q11 = q.y;
            }
            float h00 = frelu(dacc[mt][nt][0] + q00 + d0 * bb.x);
            float h01 = frelu(dacc[mt][nt][1] + q01 + d0 * bb.y);
            float h10 = frelu(dacc[mt][nt][2] + q10 + d1 * bb.x);
            float h11 = frelu(dacc[mt][nt][3] + q11 + d1 * bb.y);
            __nv_bfloat162 ph0, pl0, ph1, pl1;
            ph0.x = __float2bfloat16(h00);
            ph0.y = __float2bfloat16(h01);
            pl0.x = __float2bfloat16(h00 - __bfloat162float(ph0.x));
            pl0.y = __float2bfloat16(h01 - __bfloat162float(ph0.y));
            ph1.x = __float2bfloat16(h10);
            ph1.y = __float2bfloat16(h11);
            pl1.x = __float2bfloat16(h10 - __bfloat162float(ph1.x));
            pl1.y = __float2bfloat16(h11 - __bfloat162float(ph1.y));
            size_t o0 = ((size_t)rl0 * A_STRIDE + c) * 2;
            size_t o1 = ((size_t)rl1 * A_STRIDE + c) * 2;
            *reinterpret_cast<__nv_bfloat162*>(sm + o0) = ph0;
            *reinterpret_cast<__nv_bfloat162*>(sm + NK_OFF_ALO + o0) = pl0;
            *reinterpret_cast<__nv_bfloat162*>(sm + o1) = ph1;
            *reinterpret_cast<__nv_bfloat162*>(sm + NK_OFF_ALO + o1) = pl1;
        }
    }
    __syncthreads();

    RUN_GEMM3(g_frag_N2, ahi, alo, dacc);
    STORE_OUT(out_h, bn2, true, dacc);
}

// ---------------------------------------------------------------------------
// launch
// ---------------------------------------------------------------------------
extern "C" void kernel_launch(void* const* d_in, const int* in_sizes, int n_in,
                              void* d_out, int out_size) {
    const float* h = (const float*)d_in[0];
    const float* coords = (const float*)d_in[1];
    const int* ei = (const int*)d_in[2];
    const float* We1 = (const float*)d_in[3];
    const float* be1 = (const float*)d_in[4];
    const float* We2 = (const float*)d_in[5];
    const float* be2 = (const float*)d_in[6];
    const float* Wn1 = (const float*)d_in[7];
    const float* bn1 = (const float*)d_in[8];
    const float* Wn2 = (const float*)d_in[9];
    const float* bn2 = (const float*)d_in[10];
    const float* Wc1 = (const float*)d_in[11];
    const float* bc1 = (const float*)d_in[12];
    const float* Wc2 = (const float*)d_in[13];

    int N = in_sizes[0] / D;
    int E = in_sizes[2] / 2;

    float* out_h = (float*)d_out;
    float* out_coords = out_h + (size_t)N * D;

    cudaFuncSetAttribute(edge_kernel, cudaFuncAttributeMaxDynamicSharedMemorySize,
                         EDGE_SMEM);
    cudaFuncSetAttribute(node_prep_mma, cudaFuncAttributeMaxDynamicSharedMemorySize,
                         NP_SMEM);
    cudaFuncSetAttribute(node_mma, cudaFuncAttributeMaxDynamicSharedMemorySize,
                         NK_SMEM);

    prep_gemm<<<D, D>>>(We2, be2, Wc1, bc1, Wn1);
    pack_all<<<96, 256>>>(We1, Wn1, Wn2);

    init_kernel<<<1184, 256>>>(coords, out_coords, N);

    int nblocks = (N + NT - 1) / NT;
    node_prep_mma<<<nblocks, NTHREADS, NP_SMEM>>>(h, be1, bn1, N);

    edge_kernel<<<(E + ETILE - 1) / ETILE, NTHREADS, EDGE_SMEM>>>(
        coords, ei, We1, Wc2, out_coords, E);

    node_mma<<<nblocks, NTHREADS, NK_SMEM>>>(bn2, out_h, N);
}